// round 1
// baseline (speedup 1.0000x reference)
#include <cuda_runtime.h>
#include <cuda_bf16.h>
#include <math.h>

// Problem dims
#define D_MODEL 1024
#define D_INNER 2048
#define D_STATE 16
#define D_CONV  4
#define DT_RANK 64
#define BATCH   2
#define SEQLEN  2048
#define MROWS   (BATCH * SEQLEN)      // 4096
#define NCHUNK  16
#define CHUNK   (SEQLEN / NCHUNK)     // 128

// ---------------- scratch (device globals; no allocation in kernel_launch) --
__device__ float g_hs[MROWS * D_MODEL];          // 16 MB  normed hidden
__device__ float g_xz[(size_t)MROWS * 2 * D_INNER]; // 64 MB  in_proj output
__device__ float g_x [(size_t)MROWS * D_INNER];  // 32 MB  post conv+silu
__device__ float g_xdbl[MROWS * 96];             // 1.5 MB x_proj output
__device__ float g_dt[(size_t)MROWS * D_INNER];  // 32 MB  softplus(dt)
__device__ float g_y [(size_t)MROWS * D_INNER];  // 32 MB  gated scan output
__device__ float g_P [NCHUNK * MROWS * D_STATE]; // chunk decay products (per b,d)
__device__ float g_S [NCHUNK * MROWS * D_STATE]; // chunk local states
__device__ float g_H [NCHUNK * MROWS * D_STATE]; // chunk initial states

// ---------------- helpers ---------------------------------------------------
__device__ __forceinline__ float softplusf(float x) {
    return (x > 20.f) ? x : log1pf(__expf(x));
}

// ---------------- kernel 1: fused add + RMSNorm ------------------------------
__global__ void addnorm_kernel(const float* __restrict__ hid,
                               const float* __restrict__ res,
                               const float* __restrict__ w,
                               float* __restrict__ hs,
                               float* __restrict__ resout) {
    int row = blockIdx.x;
    int tid = threadIdx.x;                      // 256 threads, 4 floats each
    const float4* h4 = (const float4*)(hid + (size_t)row * D_MODEL);
    const float4* r4 = (const float4*)(res + (size_t)row * D_MODEL);
    float4 hv = h4[tid];
    float4 rv = r4[tid];
    float4 v;
    v.x = hv.x + rv.x; v.y = hv.y + rv.y; v.z = hv.z + rv.z; v.w = hv.w + rv.w;
    float ss = v.x * v.x + v.y * v.y + v.z * v.z + v.w * v.w;

    __shared__ float red[8];
    #pragma unroll
    for (int o = 16; o > 0; o >>= 1) ss += __shfl_down_sync(0xffffffffu, ss, o);
    int wid = tid >> 5, lane = tid & 31;
    if (lane == 0) red[wid] = ss;
    __syncthreads();
    if (wid == 0) {
        float s = (lane < 8) ? red[lane] : 0.f;
        #pragma unroll
        for (int o = 4; o > 0; o >>= 1) s += __shfl_down_sync(0xffffffffu, s, o);
        if (lane == 0) red[0] = s;
    }
    __syncthreads();
    float scale = rsqrtf(red[0] * (1.f / D_MODEL) + 1e-5f);

    if (resout) ((float4*)(resout + (size_t)row * D_MODEL))[tid] = v;
    float4 wv = ((const float4*)w)[tid];
    float4 o4;
    o4.x = v.x * scale * wv.x; o4.y = v.y * scale * wv.y;
    o4.z = v.z * scale * wv.z; o4.w = v.w * scale * wv.w;
    ((float4*)(hs + (size_t)row * D_MODEL))[tid] = o4;
}

// ---------------- kernel 2: SGEMM (classic SMEM tiled, 128x128x16, 8x8) ------
// C[M,N] = A[M,K](lda) * B[K,N](ldb)   (+ optional softplus(.+bias) epilogue)
#define BM 128
#define BN 128
#define BK 16
#define TM 8
#define TN 8
__global__ __launch_bounds__(256)
void sgemm_kernel(const float* __restrict__ A, const float* __restrict__ B,
                  float* __restrict__ C, int M, int N, int K,
                  int lda, int ldb, int ldc,
                  const float* __restrict__ bias, int epilogue) {
    __shared__ float As[BK][BM];
    __shared__ float Bs[BK][BN];
    int tid = threadIdx.x;
    int tr = tid >> 4, tc = tid & 15;           // 16x16 thread grid
    int rowBase = blockIdx.y * BM;
    int colBase = blockIdx.x * BN;

    int aRow = tid >> 2;                        // 0..63 (two passes of 64 rows)
    int aCol = (tid & 3) * 4;                   // 0,4,8,12
    int bRow = tid >> 5;                        // 0..7  (two passes of 8 rows)
    int bCol = (tid & 31) * 4;

    float acc[TM][TN] = {};
    for (int k0 = 0; k0 < K; k0 += BK) {
        #pragma unroll
        for (int i = 0; i < 2; i++) {
            int r = aRow + i * 64;
            float4 v = *(const float4*)(A + (size_t)(rowBase + r) * lda + k0 + aCol);
            As[aCol + 0][r] = v.x; As[aCol + 1][r] = v.y;
            As[aCol + 2][r] = v.z; As[aCol + 3][r] = v.w;
        }
        #pragma unroll
        for (int i = 0; i < 2; i++) {
            int r = bRow + i * 8;
            float4 v = *(const float4*)(B + (size_t)(k0 + r) * ldb + colBase + bCol);
            *(float4*)&Bs[r][bCol] = v;
        }
        __syncthreads();
        #pragma unroll
        for (int k = 0; k < BK; k++) {
            float4 a0 = *(const float4*)&As[k][tr * TM];
            float4 a1 = *(const float4*)&As[k][tr * TM + 4];
            float4 b0 = *(const float4*)&Bs[k][tc * TN];
            float4 b1 = *(const float4*)&Bs[k][tc * TN + 4];
            float ra[TM] = {a0.x, a0.y, a0.z, a0.w, a1.x, a1.y, a1.z, a1.w};
            float rb[TN] = {b0.x, b0.y, b0.z, b0.w, b1.x, b1.y, b1.z, b1.w};
            #pragma unroll
            for (int i = 0; i < TM; i++)
                #pragma unroll
                for (int j = 0; j < TN; j++)
                    acc[i][j] += ra[i] * rb[j];
        }
        __syncthreads();
    }
    #pragma unroll
    for (int i = 0; i < TM; i++) {
        int r = rowBase + tr * TM + i;
        #pragma unroll
        for (int j = 0; j < TN; j += 4) {
            int c = colBase + tc * TN + j;
            float4 v = make_float4(acc[i][j], acc[i][j+1], acc[i][j+2], acc[i][j+3]);
            if (epilogue == 1) {
                v.x = softplusf(v.x + bias[c + 0]);
                v.y = softplusf(v.y + bias[c + 1]);
                v.z = softplusf(v.z + bias[c + 2]);
                v.w = softplusf(v.w + bias[c + 3]);
            }
            *(float4*)(C + (size_t)r * ldc + c) = v;
        }
    }
}

// ---------------- kernel 3: causal depthwise conv(4) + SiLU ------------------
__global__ void conv_kernel(const float* __restrict__ xz,
                            const float* __restrict__ cw,
                            const float* __restrict__ cb,
                            float* __restrict__ xout) {
    size_t idx = (size_t)blockIdx.x * blockDim.x + threadIdx.x; // < MROWS*D_INNER
    int d = (int)(idx & (D_INNER - 1));
    int m = (int)(idx >> 11);
    int l = m & (SEQLEN - 1);
    float acc = cb[d];
    #pragma unroll
    for (int k = 0; k < D_CONV; k++) {
        int li = l + k - (D_CONV - 1);
        if (li >= 0)
            acc += xz[(size_t)(m + k - (D_CONV - 1)) * (2 * D_INNER) + d] * cw[d * D_CONV + k];
    }
    // SiLU
    acc = acc / (1.f + __expf(-acc));
    xout[idx] = acc;
}

// ---------------- kernel 4: thin GEMM x @ x_proj_w [2048,96] -----------------
// 8 rows per block, 128 threads (threads 0..95 compute one output column each)
__global__ __launch_bounds__(128)
void xproj_kernel(const float* __restrict__ X, const float* __restrict__ W,
                  float* __restrict__ out) {
    __shared__ float xs[8][128];
    int m0 = blockIdx.x * 8;
    int n = threadIdx.x;
    float acc[8] = {};
    for (int kc = 0; kc < D_INNER; kc += 128) {
        __syncthreads();
        #pragma unroll
        for (int r = 0; r < 8; r++)
            xs[r][threadIdx.x] = X[(size_t)(m0 + r) * D_INNER + kc + threadIdx.x];
        __syncthreads();
        if (n < 96) {
            #pragma unroll 4
            for (int k = 0; k < 128; k++) {
                float w = W[(size_t)(kc + k) * 96 + n];
                #pragma unroll
                for (int r = 0; r < 8; r++) acc[r] += xs[r][k] * w;
            }
        }
    }
    if (n < 96) {
        #pragma unroll
        for (int r = 0; r < 8; r++) out[(size_t)(m0 + r) * 96 + n] = acc[r];
    }
}

// ---------------- kernel 6a: scan pass A (per-chunk decay product + state) ---
__global__ __launch_bounds__(256)
void scanA_kernel(const float* __restrict__ dt, const float* __restrict__ x,
                  const float* __restrict__ xdbl, const float* __restrict__ A_log,
                  float* __restrict__ Pout, float* __restrict__ Sout) {
    int d = blockIdx.x * blockDim.x + threadIdx.x;
    int b = blockIdx.y, c = blockIdx.z;
    float Ae[D_STATE];
    #pragma unroll
    for (int n = 0; n < D_STATE; n++) Ae[n] = -__expf(A_log[d * D_STATE + n]);
    float h[D_STATE] = {};
    float P[D_STATE];
    #pragma unroll
    for (int n = 0; n < D_STATE; n++) P[n] = 1.f;

    int m0 = b * SEQLEN + c * CHUNK;
    for (int t = 0; t < CHUNK; t++) {
        int m = m0 + t;
        float dtv = dt[(size_t)m * D_INNER + d];
        float xv  = x [(size_t)m * D_INNER + d];
        float cb = dtv * xv;
        const float* br = xdbl + (size_t)m * 96 + DT_RANK;
        #pragma unroll
        for (int n = 0; n < D_STATE; n++) {
            float dA = __expf(dtv * Ae[n]);
            P[n] *= dA;
            h[n] = h[n] * dA + cb * br[n];
        }
    }
    size_t o = (((size_t)c * BATCH + b) * D_INNER + d) * D_STATE;
    #pragma unroll
    for (int n = 0; n < D_STATE; n++) { Pout[o + n] = P[n]; Sout[o + n] = h[n]; }
}

// ---------------- kernel 6b: sequential chunk combine ------------------------
__global__ void combine_kernel(const float* __restrict__ P,
                               const float* __restrict__ S,
                               float* __restrict__ H) {
    int idx = blockIdx.x * blockDim.x + threadIdx.x;   // < BATCH*D_INNER
    int d = idx & (D_INNER - 1);
    int b = idx >> 11;
    float h[D_STATE] = {};
    for (int c = 0; c < NCHUNK; c++) {
        size_t o = (((size_t)c * BATCH + b) * D_INNER + d) * D_STATE;
        #pragma unroll
        for (int n = 0; n < D_STATE; n++) {
            H[o + n] = h[n];
            h[n] = h[n] * P[o + n] + S[o + n];
        }
    }
}

// ---------------- kernel 6c: scan pass C (emit y, fuse D-skip + SiLU gate) ---
__global__ __launch_bounds__(256)
void scanC_kernel(const float* __restrict__ dt, const float* __restrict__ x,
                  const float* __restrict__ xdbl, const float* __restrict__ A_log,
                  const float* __restrict__ H, const float* __restrict__ xz,
                  const float* __restrict__ Dskip, float* __restrict__ yout) {
    int d = blockIdx.x * blockDim.x + threadIdx.x;
    int b = blockIdx.y, c = blockIdx.z;
    float Ae[D_STATE];
    #pragma unroll
    for (int n = 0; n < D_STATE; n++) Ae[n] = -__expf(A_log[d * D_STATE + n]);
    float h[D_STATE];
    size_t o = (((size_t)c * BATCH + b) * D_INNER + d) * D_STATE;
    #pragma unroll
    for (int n = 0; n < D_STATE; n++) h[n] = H[o + n];
    float Dv = Dskip[d];

    int m0 = b * SEQLEN + c * CHUNK;
    for (int t = 0; t < CHUNK; t++) {
        int m = m0 + t;
        float dtv = dt[(size_t)m * D_INNER + d];
        float xv  = x [(size_t)m * D_INNER + d];
        float cb = dtv * xv;
        const float* br = xdbl + (size_t)m * 96 + DT_RANK;
        const float* cr = br + D_STATE;
        float y = 0.f;
        #pragma unroll
        for (int n = 0; n < D_STATE; n++) {
            float dA = __expf(dtv * Ae[n]);
            h[n] = h[n] * dA + cb * br[n];
            y += h[n] * cr[n];
        }
        float zv = xz[(size_t)m * (2 * D_INNER) + D_INNER + d];
        float sz = zv / (1.f + __expf(-zv));
        yout[(size_t)m * D_INNER + d] = (y + xv * Dv) * sz;
    }
}

// ---------------- launch ------------------------------------------------------
extern "C" void kernel_launch(void* const* d_in, const int* in_sizes, int n_in,
                              void* d_out, int out_size) {
    const float* hidden   = (const float*)d_in[0];
    const float* residual = (const float*)d_in[1];
    const float* norm_w   = (const float*)d_in[2];
    const float* in_proj  = (const float*)d_in[3];
    const float* conv_w   = (const float*)d_in[4];
    const float* conv_b   = (const float*)d_in[5];
    const float* x_proj   = (const float*)d_in[6];
    const float* dt_proj  = (const float*)d_in[7];
    const float* dt_b     = (const float*)d_in[8];
    const float* A_log    = (const float*)d_in[9];
    const float* D_skip   = (const float*)d_in[10];
    const float* out_proj = (const float*)d_in[11];
    float* out = (float*)d_out;

    float *hs, *xz, *x, *xdbl, *dt, *y, *P, *S, *H;
    cudaGetSymbolAddress((void**)&hs,   g_hs);
    cudaGetSymbolAddress((void**)&xz,   g_xz);
    cudaGetSymbolAddress((void**)&x,    g_x);
    cudaGetSymbolAddress((void**)&xdbl, g_xdbl);
    cudaGetSymbolAddress((void**)&dt,   g_dt);
    cudaGetSymbolAddress((void**)&y,    g_y);
    cudaGetSymbolAddress((void**)&P,    g_P);
    cudaGetSymbolAddress((void**)&S,    g_S);
    cudaGetSymbolAddress((void**)&H,    g_H);

    const int OUT1 = MROWS * D_MODEL;
    float* resout = (out_size >= 2 * OUT1) ? out + OUT1 : nullptr;

    // 1. add + RMSNorm (also writes residual output)
    addnorm_kernel<<<MROWS, 256>>>(hidden, residual, norm_w, hs, resout);

    // 2. xz = hs @ in_proj_w   [4096,1024]x[1024,4096]
    sgemm_kernel<<<dim3(2 * D_INNER / BN, MROWS / BM), 256>>>(
        hs, in_proj, xz, MROWS, 2 * D_INNER, D_MODEL,
        D_MODEL, 2 * D_INNER, 2 * D_INNER, nullptr, 0);

    // 3. causal depthwise conv + SiLU on x half
    conv_kernel<<<(MROWS * D_INNER) / 256, 256>>>(xz, conv_w, conv_b, x);

    // 4. x_dbl = x @ x_proj_w  [4096,2048]x[2048,96]
    xproj_kernel<<<MROWS / 8, 128>>>(x, x_proj, xdbl);

    // 5. dt = softplus(x_dbl[:, :64] @ dt_proj_w + dt_b)  [4096,64]x[64,2048]
    sgemm_kernel<<<dim3(D_INNER / BN, MROWS / BM), 256>>>(
        xdbl, dt_proj, dt, MROWS, D_INNER, DT_RANK,
        96, D_INNER, D_INNER, dt_b, 1);

    // 6. selective scan: chunked 3-pass
    scanA_kernel<<<dim3(D_INNER / 256, BATCH, NCHUNK), 256>>>(dt, x, xdbl, A_log, P, S);
    combine_kernel<<<(BATCH * D_INNER) / 256, 256>>>(P, S, H);
    scanC_kernel<<<dim3(D_INNER / 256, BATCH, NCHUNK), 256>>>(dt, x, xdbl, A_log, H, xz, D_skip, y);

    // 7. out = y @ out_proj_w  [4096,2048]x[2048,1024]
    sgemm_kernel<<<dim3(D_MODEL / BN, MROWS / BM), 256>>>(
        y, out_proj, out, MROWS, D_MODEL, D_INNER,
        D_INNER, D_MODEL, D_MODEL, nullptr, 0);
}

// round 3
// speedup vs baseline: 1.8870x; 1.8870x over previous
#include <cuda_runtime.h>
#include <cuda_bf16.h>
#include <math.h>
#include <stdint.h>

// Problem dims
#define D_MODEL 1024
#define D_INNER 2048
#define D_STATE 16
#define D_CONV  4
#define DT_RANK 64
#define BATCH   2
#define SEQLEN  2048
#define MROWS   (BATCH * SEQLEN)      // 4096
#define NCHUNK  16
#define CHUNK   (SEQLEN / NCHUNK)     // 128

// ---------------- scratch (device globals) ----------------------------------
__device__ __align__(256) float g_xz[(size_t)MROWS * 2 * D_INNER]; // 64 MB
__device__ __align__(256) float g_x [(size_t)MROWS * D_INNER];     // 32 MB
__device__ __align__(256) float g_xdbl[MROWS * 96];
__device__ __align__(256) float g_dt[(size_t)MROWS * D_INNER];     // 32 MB
__device__ __align__(256) float g_P [NCHUNK * MROWS * D_STATE];
__device__ __align__(256) float g_S [NCHUNK * MROWS * D_STATE];
__device__ __align__(256) float g_H [NCHUNK * MROWS * D_STATE];
// split-bf16 A' matrices [M, 3K] = [hi | hi | lo]
__device__ __align__(256) __nv_bfloat16 g_hsb [(size_t)MROWS * 3 * D_MODEL];
__device__ __align__(256) __nv_bfloat16 g_xb  [(size_t)MROWS * 3 * D_INNER];
__device__ __align__(256) __nv_bfloat16 g_yb  [(size_t)MROWS * 3 * D_INNER];
__device__ __align__(256) __nv_bfloat16 g_dtab[(size_t)MROWS * 3 * DT_RANK];
// split-bf16 B' matrices [N, 3K] = [hi | lo | hi] (transposed weights)
__device__ __align__(256) __nv_bfloat16 g_wib[(size_t)(2*D_INNER) * 3 * D_MODEL];
__device__ __align__(256) __nv_bfloat16 g_wxb[(size_t)128 * 3 * D_INNER];   // N padded to 128; rows 96..127 stay zero
__device__ __align__(256) __nv_bfloat16 g_wdb[(size_t)D_INNER * 3 * DT_RANK];
__device__ __align__(256) __nv_bfloat16 g_wob[(size_t)D_MODEL * 3 * D_INNER];

// ---------------- helpers ---------------------------------------------------
__device__ __forceinline__ float softplusf(float x) {
    return (x > 20.f) ? x : log1pf(__expf(x));
}

__device__ __forceinline__ uint32_t smem_u32(const void* p) {
    uint32_t a;
    asm("{ .reg .u64 t; cvta.to.shared.u64 t, %1; cvt.u32.u64 %0, t; }" : "=r"(a) : "l"(p));
    return a;
}

__device__ __forceinline__ void split_bf16(float v, __nv_bfloat16& hi, __nv_bfloat16& lo) {
    hi = __float2bfloat16(v);
    lo = __float2bfloat16(v - __bfloat162float(hi));
}

__device__ __forceinline__ void ldsm_x4(uint32_t& r0, uint32_t& r1, uint32_t& r2, uint32_t& r3,
                                        uint32_t addr) {
    asm volatile("ldmatrix.sync.aligned.m8n8.x4.shared.b16 {%0,%1,%2,%3}, [%4];"
                 : "=r"(r0), "=r"(r1), "=r"(r2), "=r"(r3) : "r"(addr));
}

__device__ __forceinline__ void mma16816(float& c0, float& c1, float& c2, float& c3,
                                         uint32_t a0, uint32_t a1, uint32_t a2, uint32_t a3,
                                         uint32_t b0, uint32_t b1) {
    asm volatile("mma.sync.aligned.m16n8k16.row.col.f32.bf16.bf16.f32 "
                 "{%0,%1,%2,%3}, {%4,%5,%6,%7}, {%8,%9}, {%0,%1,%2,%3};"
                 : "+f"(c0), "+f"(c1), "+f"(c2), "+f"(c3)
                 : "r"(a0), "r"(a1), "r"(a2), "r"(a3), "r"(b0), "r"(b1));
}

#define CP_ASYNC16(dst, src) \
    asm volatile("cp.async.cg.shared.global [%0], [%1], 16;" :: "r"(dst), "l"(src))
#define CP_COMMIT() asm volatile("cp.async.commit_group;" ::: "memory")
#define CP_WAIT2()  asm volatile("cp.async.wait_group 2;" ::: "memory")

// ---------------- kernel 1: fused add + RMSNorm -> split bf16 hs' ------------
__global__ void addnorm_kernel(const float* __restrict__ hid,
                               const float* __restrict__ res,
                               const float* __restrict__ w,
                               __nv_bfloat16* __restrict__ hsb,
                               float* __restrict__ resout) {
    int row = blockIdx.x;
    int tid = threadIdx.x;                      // 256 threads, 4 floats each
    const float4* h4 = (const float4*)(hid + (size_t)row * D_MODEL);
    const float4* r4 = (const float4*)(res + (size_t)row * D_MODEL);
    float4 hv = h4[tid];
    float4 rv = r4[tid];
    float4 v;
    v.x = hv.x + rv.x; v.y = hv.y + rv.y; v.z = hv.z + rv.z; v.w = hv.w + rv.w;
    float ss = v.x * v.x + v.y * v.y + v.z * v.z + v.w * v.w;

    __shared__ float red[8];
    #pragma unroll
    for (int o = 16; o > 0; o >>= 1) ss += __shfl_down_sync(0xffffffffu, ss, o);
    int wid = tid >> 5, lane = tid & 31;
    if (lane == 0) red[wid] = ss;
    __syncthreads();
    if (wid == 0) {
        float s = (lane < 8) ? red[lane] : 0.f;
        #pragma unroll
        for (int o = 4; o > 0; o >>= 1) s += __shfl_down_sync(0xffffffffu, s, o);
        if (lane == 0) red[0] = s;
    }
    __syncthreads();
    float scale = rsqrtf(red[0] * (1.f / D_MODEL) + 1e-5f);

    if (resout) ((float4*)(resout + (size_t)row * D_MODEL))[tid] = v;
    float4 wv = ((const float4*)w)[tid];
    float o0 = v.x * scale * wv.x, o1 = v.y * scale * wv.y;
    float o2 = v.z * scale * wv.z, o3 = v.w * scale * wv.w;

    __nv_bfloat16 h0, h1, h2, h3, l0, l1, l2, l3;
    split_bf16(o0, h0, l0); split_bf16(o1, h1, l1);
    split_bf16(o2, h2, l2); split_bf16(o3, h3, l3);
    __nv_bfloat16* base = hsb + (size_t)row * 3 * D_MODEL + tid * 4;
    *(__nv_bfloat162*)(base + 0) = __halves2bfloat162(h0, h1);
    *(__nv_bfloat162*)(base + 2) = __halves2bfloat162(h2, h3);
    *(__nv_bfloat162*)(base + D_MODEL + 0) = __halves2bfloat162(h0, h1);
    *(__nv_bfloat162*)(base + D_MODEL + 2) = __halves2bfloat162(h2, h3);
    *(__nv_bfloat162*)(base + 2 * D_MODEL + 0) = __halves2bfloat162(l0, l1);
    *(__nv_bfloat162*)(base + 2 * D_MODEL + 2) = __halves2bfloat162(l2, l3);
}

// ---------------- weight split+transpose: W[K,N] -> B'[N,3K]=[hi,lo,hi] ------
__global__ void splitB_kernel(const float* __restrict__ W,
                              __nv_bfloat16* __restrict__ out, int K, int N) {
    __shared__ float t[32][33];
    int k0 = blockIdx.y * 32, n0 = blockIdx.x * 32;
    t[threadIdx.y][threadIdx.x] = W[(size_t)(k0 + threadIdx.y) * N + n0 + threadIdx.x];
    __syncthreads();
    float v = t[threadIdx.x][threadIdx.y];      // = W[k0+tx][n0+ty]
    int n = n0 + threadIdx.y, k = k0 + threadIdx.x;
    __nv_bfloat16 hi, lo;
    split_bf16(v, hi, lo);
    size_t o = (size_t)n * 3 * K;
    out[o + k] = hi;
    out[o + K + k] = lo;
    out[o + 2 * K + k] = hi;
}

// ---------------- activation split: in[M,K](ld) -> A'[M,3K]=[hi,hi,lo] -------
__global__ void splitA_kernel(const float* __restrict__ in,
                              __nv_bfloat16* __restrict__ out, int K, int ld) {
    size_t idx = (size_t)blockIdx.x * blockDim.x + threadIdx.x;
    int k = (int)(idx % K);
    size_t m = idx / K;
    float v = in[m * ld + k];
    __nv_bfloat16 hi, lo;
    split_bf16(v, hi, lo);
    size_t o = m * 3 * K;
    out[o + k] = hi; out[o + K + k] = hi; out[o + 2 * K + k] = lo;
}

// ---------------- mma.sync bf16 GEMM: C[M,N] = A'[M,Kp] * B'[N,Kp]^T ---------
// CTA tile 128x128, BK=64 bf16 (128 bytes/row), 3-stage cp.async pipeline.
// 8 warps: warp grid 2(M) x 4(N); warp tile 64x32.
#define STAGES 3
#define TILEB  16384                        // one operand tile: 128 rows x 128 bytes
#define GEMM_SMEM (STAGES * 2 * TILEB)      // 96 KB

__device__ __forceinline__ void load_tile_pair(uint32_t st,
                                               const char* Asrc, const char* Bsrc,
                                               size_t rowBytes, int tid) {
    #pragma unroll
    for (int j = 0; j < 4; j++) {
        int off = (tid + j * 256) * 16;          // 0..16383
        int row = off >> 7, bc = off & 127;
        uint32_t sw = (uint32_t)(row * 128 + (bc ^ ((row & 7) << 4)));
        CP_ASYNC16(st + sw, Asrc + (size_t)row * rowBytes + bc);
    }
    #pragma unroll
    for (int j = 0; j < 4; j++) {
        int off = (tid + j * 256) * 16;
        int row = off >> 7, bc = off & 127;
        uint32_t sw = (uint32_t)(row * 128 + (bc ^ ((row & 7) << 4)));
        CP_ASYNC16(st + TILEB + sw, Bsrc + (size_t)row * rowBytes + bc);
    }
    CP_COMMIT();
}

__global__ __launch_bounds__(256)
void gemm_bf16_kernel(const __nv_bfloat16* __restrict__ A,
                      const __nv_bfloat16* __restrict__ B,
                      float* __restrict__ C,
                      int Kp, int ldc, int Nstore,
                      const float* __restrict__ bias, int epilogue) {
    extern __shared__ char smem[];
    uint32_t sb = smem_u32(smem);
    int tid = threadIdx.x;
    int wid = tid >> 5, lane = tid & 31;
    int mBase = blockIdx.y * 128;
    int nBase = blockIdx.x * 128;
    int m0w = (wid >> 2) * 64;                  // warp M offset in tile
    int n0w = (wid & 3) * 32;                   // warp N offset in tile

    const char* Ab = (const char*)A + (size_t)mBase * Kp * 2;
    const char* Bb = (const char*)B + (size_t)nBase * Kp * 2;
    const size_t rowBytes = (size_t)Kp * 2;
    const int nIter = Kp / 64;

    float c[4][4][4];                           // [mi][n8][reg]
    #pragma unroll
    for (int i = 0; i < 4; i++)
        #pragma unroll
        for (int j = 0; j < 4; j++)
            #pragma unroll
            for (int r = 0; r < 4; r++) c[i][j][r] = 0.f;

    int pre = nIter < STAGES ? nIter : STAGES;
    for (int s = 0; s < pre; s++)
        load_tile_pair(sb + s * 2 * TILEB, Ab + (size_t)s * 128, Bb + (size_t)s * 128, rowBytes, tid);

    int laneM = lane & 15, laneH = lane >> 4;   // ldmatrix addressing

    for (int i = 0; i < nIter; i++) {
        uint32_t st = sb + (uint32_t)(i % STAGES) * 2 * TILEB;
        CP_WAIT2();
        __syncthreads();

        #pragma unroll
        for (int ks = 0; ks < 4; ks++) {
            int bc = ks * 32 + laneH * 16;      // byte col within 128B row
            uint32_t a[4][4], b[2][4];
            #pragma unroll
            for (int mi = 0; mi < 4; mi++) {
                int row = m0w + mi * 16 + laneM;
                uint32_t ad = st + row * 128 + (bc ^ ((row & 7) << 4));
                ldsm_x4(a[mi][0], a[mi][1], a[mi][2], a[mi][3], ad);
            }
            #pragma unroll
            for (int ng = 0; ng < 2; ng++) {
                int row = n0w + ng * 16 + laneM;
                uint32_t bd = st + TILEB + row * 128 + (bc ^ ((row & 7) << 4));
                ldsm_x4(b[ng][0], b[ng][1], b[ng][2], b[ng][3], bd);
            }
            #pragma unroll
            for (int mi = 0; mi < 4; mi++)
                #pragma unroll
                for (int n8 = 0; n8 < 4; n8++) {
                    int ng = n8 >> 1, half = n8 & 1;
                    mma16816(c[mi][n8][0], c[mi][n8][1], c[mi][n8][2], c[mi][n8][3],
                             a[mi][0], a[mi][1], a[mi][2], a[mi][3],
                             b[ng][half], b[ng][half + 2]);
                }
        }
        __syncthreads();
        int nx = i + STAGES;
        if (nx < nIter)
            load_tile_pair(st, Ab + (size_t)nx * 128, Bb + (size_t)nx * 128, rowBytes, tid);
        else
            CP_COMMIT();                        // empty group keeps wait_group count aligned
    }

    // epilogue: write fp32 from fragments
    int rlo = lane >> 2;
    int cc0 = 2 * (lane & 3);
    #pragma unroll
    for (int mi = 0; mi < 4; mi++) {
        int r0 = mBase + m0w + mi * 16 + rlo;
        #pragma unroll
        for (int n8 = 0; n8 < 4; n8++) {
            int col = nBase + n0w + n8 * 8 + cc0;
            if (col < Nstore) {
                float v0 = c[mi][n8][0], v1 = c[mi][n8][1];
                float v2 = c[mi][n8][2], v3 = c[mi][n8][3];
                if (epilogue == 1) {
                    v0 = softplusf(v0 + bias[col]);
                    v1 = softplusf(v1 + bias[col + 1]);
                    v2 = softplusf(v2 + bias[col]);
                    v3 = softplusf(v3 + bias[col + 1]);
                }
                *(float2*)(C + (size_t)r0 * ldc + col) = make_float2(v0, v1);
                *(float2*)(C + (size_t)(r0 + 8) * ldc + col) = make_float2(v2, v3);
            }
        }
    }
}

// ---------------- causal depthwise conv(4) + SiLU -> x fp32 + x' split -------
__global__ void conv_kernel(const float* __restrict__ xz,
                            const float* __restrict__ cw,
                            const float* __restrict__ cb,
                            float* __restrict__ xout,
                            __nv_bfloat16* __restrict__ xb) {
    size_t idx = (size_t)blockIdx.x * blockDim.x + threadIdx.x;
    int d = (int)(idx & (D_INNER - 1));
    int m = (int)(idx >> 11);
    int l = m & (SEQLEN - 1);
    float acc = cb[d];
    #pragma unroll
    for (int k = 0; k < D_CONV; k++) {
        int li = l + k - (D_CONV - 1);
        if (li >= 0)
            acc += xz[(size_t)(m + k - (D_CONV - 1)) * (2 * D_INNER) + d] * cw[d * D_CONV + k];
    }
    acc = acc / (1.f + __expf(-acc));
    xout[idx] = acc;
    __nv_bfloat16 hi, lo;
    split_bf16(acc, hi, lo);
    size_t o = (size_t)m * 3 * D_INNER;
    xb[o + d] = hi; xb[o + D_INNER + d] = hi; xb[o + 2 * D_INNER + d] = lo;
}

// ---------------- scan pass A -------------------------------------------------
__global__ __launch_bounds__(256)
void scanA_kernel(const float* __restrict__ dt, const float* __restrict__ x,
                  const float* __restrict__ xdbl, const float* __restrict__ A_log,
                  float* __restrict__ Pout, float* __restrict__ Sout) {
    int d = blockIdx.x * blockDim.x + threadIdx.x;
    int b = blockIdx.y, c = blockIdx.z;
    float Ae[D_STATE];
    #pragma unroll
    for (int n = 0; n < D_STATE; n++) Ae[n] = -__expf(A_log[d * D_STATE + n]);
    float h[D_STATE] = {};
    float P[D_STATE];
    #pragma unroll
    for (int n = 0; n < D_STATE; n++) P[n] = 1.f;

    int m0 = b * SEQLEN + c * CHUNK;
    for (int t = 0; t < CHUNK; t++) {
        int m = m0 + t;
        float dtv = dt[(size_t)m * D_INNER + d];
        float xv  = x [(size_t)m * D_INNER + d];
        float cb = dtv * xv;
        const float* br = xdbl + (size_t)m * 96 + DT_RANK;
        #pragma unroll
        for (int n = 0; n < D_STATE; n++) {
            float dA = __expf(dtv * Ae[n]);
            P[n] *= dA;
            h[n] = h[n] * dA + cb * br[n];
        }
    }
    size_t o = (((size_t)c * BATCH + b) * D_INNER + d) * D_STATE;
    #pragma unroll
    for (int n = 0; n < D_STATE; n++) { Pout[o + n] = P[n]; Sout[o + n] = h[n]; }
}

// ---------------- chunk combine ----------------------------------------------
__global__ void combine_kernel(const float* __restrict__ P,
                               const float* __restrict__ S,
                               float* __restrict__ H) {
    int idx = blockIdx.x * blockDim.x + threadIdx.x;
    int d = idx & (D_INNER - 1);
    int b = idx >> 11;
    float h[D_STATE] = {};
    for (int c = 0; c < NCHUNK; c++) {
        size_t o = (((size_t)c * BATCH + b) * D_INNER + d) * D_STATE;
        #pragma unroll
        for (int n = 0; n < D_STATE; n++) {
            H[o + n] = h[n];
            h[n] = h[n] * P[o + n] + S[o + n];
        }
    }
}

// ---------------- scan pass C: emit y' split bf16 ----------------------------
__global__ __launch_bounds__(256)
void scanC_kernel(const float* __restrict__ dt, const float* __restrict__ x,
                  const float* __restrict__ xdbl, const float* __restrict__ A_log,
                  const float* __restrict__ H, const float* __restrict__ xz,
                  const float* __restrict__ Dskip, __nv_bfloat16* __restrict__ yb) {
    int d = blockIdx.x * blockDim.x + threadIdx.x;
    int b = blockIdx.y, c = blockIdx.z;
    float Ae[D_STATE];
    #pragma unroll
    for (int n = 0; n < D_STATE; n++) Ae[n] = -__expf(A_log[d * D_STATE + n]);
    float h[D_STATE];
    size_t o = (((size_t)c * BATCH + b) * D_INNER + d) * D_STATE;
    #pragma unroll
    for (int n = 0; n < D_STATE; n++) h[n] = H[o + n];
    float Dv = Dskip[d];

    int m0 = b * SEQLEN + c * CHUNK;
    for (int t = 0; t < CHUNK; t++) {
        int m = m0 + t;
        float dtv = dt[(size_t)m * D_INNER + d];
        float xv  = x [(size_t)m * D_INNER + d];
        float cbv = dtv * xv;
        const float* br = xdbl + (size_t)m * 96 + DT_RANK;
        const float* cr = br + D_STATE;
        float y = 0.f;
        #pragma unroll
        for (int n = 0; n < D_STATE; n++) {
            float dA = __expf(dtv * Ae[n]);
            h[n] = h[n] * dA + cbv * br[n];
            y += h[n] * cr[n];
        }
        float zv = xz[(size_t)m * (2 * D_INNER) + D_INNER + d];
        float sz = zv / (1.f + __expf(-zv));
        float yv = (y + xv * Dv) * sz;
        __nv_bfloat16 hi, lo;
        split_bf16(yv, hi, lo);
        size_t oy = (size_t)m * 3 * D_INNER;
        yb[oy + d] = hi; yb[oy + D_INNER + d] = hi; yb[oy + 2 * D_INNER + d] = lo;
    }
}

// ---------------- launch ------------------------------------------------------
extern "C" void kernel_launch(void* const* d_in, const int* in_sizes, int n_in,
                              void* d_out, int out_size) {
    const float* hidden   = (const float*)d_in[0];
    const float* residual = (const float*)d_in[1];
    const float* norm_w   = (const float*)d_in[2];
    const float* in_proj  = (const float*)d_in[3];
    const float* conv_w   = (const float*)d_in[4];
    const float* conv_b   = (const float*)d_in[5];
    const float* x_proj   = (const float*)d_in[6];
    const float* dt_proj  = (const float*)d_in[7];
    const float* dt_b     = (const float*)d_in[8];
    const float* A_log    = (const float*)d_in[9];
    const float* D_skip   = (const float*)d_in[10];
    const float* out_proj = (const float*)d_in[11];
    float* out = (float*)d_out;

    float *xz, *x, *xdbl, *dt, *P, *S, *H;
    __nv_bfloat16 *hsb, *xb, *yb, *dtab, *wib, *wxb, *wdb, *wob;
    cudaGetSymbolAddress((void**)&xz,   g_xz);
    cudaGetSymbolAddress((void**)&x,    g_x);
    cudaGetSymbolAddress((void**)&xdbl, g_xdbl);
    cudaGetSymbolAddress((void**)&dt,   g_dt);
    cudaGetSymbolAddress((void**)&P,    g_P);
    cudaGetSymbolAddress((void**)&S,    g_S);
    cudaGetSymbolAddress((void**)&H,    g_H);
    cudaGetSymbolAddress((void**)&hsb,  g_hsb);
    cudaGetSymbolAddress((void**)&xb,   g_xb);
    cudaGetSymbolAddress((void**)&yb,   g_yb);
    cudaGetSymbolAddress((void**)&dtab, g_dtab);
    cudaGetSymbolAddress((void**)&wib,  g_wib);
    cudaGetSymbolAddress((void**)&wxb,  g_wxb);
    cudaGetSymbolAddress((void**)&wdb,  g_wdb);
    cudaGetSymbolAddress((void**)&wob,  g_wob);

    cudaFuncSetAttribute(gemm_bf16_kernel, cudaFuncAttributeMaxDynamicSharedMemorySize, GEMM_SMEM);

    const int OUT1 = MROWS * D_MODEL;
    float* resout = (out_size >= 2 * OUT1) ? out + OUT1 : nullptr;

    dim3 b32(32, 32);

    // weight splits (independent of activations; issue first)
    splitB_kernel<<<dim3(2 * D_INNER / 32, D_MODEL / 32), b32>>>(in_proj, wib, D_MODEL, 2 * D_INNER);
    splitB_kernel<<<dim3(96 / 32, D_INNER / 32), b32>>>(x_proj, wxb, D_INNER, 96);
    splitB_kernel<<<dim3(D_INNER / 32, DT_RANK / 32), b32>>>(dt_proj, wdb, DT_RANK, D_INNER);
    splitB_kernel<<<dim3(D_MODEL / 32, D_INNER / 32), b32>>>(out_proj, wob, D_INNER, D_MODEL);

    // 1. add + RMSNorm -> hs' (and residual output)
    addnorm_kernel<<<MROWS, 256>>>(hidden, residual, norm_w, hsb, resout);

    // 2. xz = hs @ in_proj_w   (M=4096, N=4096, Kp=3072)
    gemm_bf16_kernel<<<dim3(2 * D_INNER / 128, MROWS / 128), 256, GEMM_SMEM>>>(
        hsb, wib, xz, 3 * D_MODEL, 2 * D_INNER, 2 * D_INNER, nullptr, 0);

    // 3. conv + SiLU -> x fp32 + x' split
    conv_kernel<<<(MROWS * D_INNER) / 256, 256>>>(xz, conv_w, conv_b, x, xb);

    // 4. x_dbl = x @ x_proj_w (N padded to 128, store 96; Kp=6144)
    gemm_bf16_kernel<<<dim3(1, MROWS / 128), 256, GEMM_SMEM>>>(
        xb, wxb, xdbl, 3 * D_INNER, 96, 96, nullptr, 0);

    // 5. dt = softplus(x_dbl[:, :64] @ dt_proj_w + dt_b)  (Kp=192)
    splitA_kernel<<<(MROWS * DT_RANK) / 256, 256>>>(xdbl, dtab, DT_RANK, 96);
    gemm_bf16_kernel<<<dim3(D_INNER / 128, MROWS / 128), 256, GEMM_SMEM>>>(
        dtab, wdb, dt, 3 * DT_RANK, D_INNER, D_INNER, dt_b, 1);

    // 6. selective scan: chunked 3-pass (scanC emits y' split)
    scanA_kernel<<<dim3(D_INNER / 256, BATCH, NCHUNK), 256>>>(dt, x, xdbl, A_log, P, S);
    combine_kernel<<<(BATCH * D_INNER) / 256, 256>>>(P, S, H);
    scanC_kernel<<<dim3(D_INNER / 256, BATCH, NCHUNK), 256>>>(dt, x, xdbl, A_log, H, xz, D_skip, yb);

    // 7. out = y @ out_proj_w  (Kp=6144)
    gemm_bf16_kernel<<<dim3(D_MODEL / 128, MROWS / 128), 256, GEMM_SMEM>>>(
        yb, wob, out, 3 * D_INNER, D_MODEL, D_MODEL, nullptr, 0);
}

// round 4
// speedup vs baseline: 1.9071x; 1.0107x over previous
#include <cuda_runtime.h>
#include <cuda_bf16.h>
#include <math.h>
#include <stdint.h>

// Problem dims
#define D_MODEL 1024
#define D_INNER 2048
#define D_STATE 16
#define D_CONV  4
#define DT_RANK 64
#define BATCH   2
#define SEQLEN  2048
#define MROWS   (BATCH * SEQLEN)      // 4096
#define NCHUNK  16
#define CHUNK   (SEQLEN / NCHUNK)     // 128
#define KSPLIT  8                     // xproj split-K factor

// ---------------- scratch (device globals) ----------------------------------
__device__ __align__(256) float g_xz[(size_t)MROWS * 2 * D_INNER]; // 64 MB
__device__ __align__(256) float g_x [(size_t)MROWS * D_INNER];     // 32 MB
__device__ __align__(256) float g_xdbl[MROWS * 96];
__device__ __align__(256) float g_xpart[(size_t)KSPLIT * MROWS * 96]; // 12.6 MB
__device__ __align__(256) float g_dt[(size_t)MROWS * D_INNER];     // 32 MB
__device__ __align__(256) float g_P [NCHUNK * MROWS * D_STATE];
__device__ __align__(256) float g_S [NCHUNK * MROWS * D_STATE];
__device__ __align__(256) float g_H [NCHUNK * MROWS * D_STATE];
// split-bf16 A' matrices [M, 3K] = [hi | hi | lo]
__device__ __align__(256) __nv_bfloat16 g_hsb [(size_t)MROWS * 3 * D_MODEL];
__device__ __align__(256) __nv_bfloat16 g_xb  [(size_t)MROWS * 3 * D_INNER];
__device__ __align__(256) __nv_bfloat16 g_yb  [(size_t)MROWS * 3 * D_INNER];
__device__ __align__(256) __nv_bfloat16 g_dtab[(size_t)MROWS * 3 * DT_RANK];
// split-bf16 B' matrices [N, 3K] = [hi | lo | hi] (transposed weights)
__device__ __align__(256) __nv_bfloat16 g_wib[(size_t)(2*D_INNER) * 3 * D_MODEL];
__device__ __align__(256) __nv_bfloat16 g_wxb[(size_t)128 * 3 * D_INNER];   // N padded to 128; rows 96..127 stay zero
__device__ __align__(256) __nv_bfloat16 g_wdb[(size_t)D_INNER * 3 * DT_RANK];
__device__ __align__(256) __nv_bfloat16 g_wob[(size_t)D_MODEL * 3 * D_INNER];

// ---------------- helpers ---------------------------------------------------
__device__ __forceinline__ float softplusf(float x) {
    return (x > 20.f) ? x : log1pf(__expf(x));
}

__device__ __forceinline__ uint32_t smem_u32(const void* p) {
    uint32_t a;
    asm("{ .reg .u64 t; cvta.to.shared.u64 t, %1; cvt.u32.u64 %0, t; }" : "=r"(a) : "l"(p));
    return a;
}

__device__ __forceinline__ void split_bf16(float v, __nv_bfloat16& hi, __nv_bfloat16& lo) {
    hi = __float2bfloat16(v);
    lo = __float2bfloat16(v - __bfloat162float(hi));
}

__device__ __forceinline__ void ldsm_x4(uint32_t& r0, uint32_t& r1, uint32_t& r2, uint32_t& r3,
                                        uint32_t addr) {
    asm volatile("ldmatrix.sync.aligned.m8n8.x4.shared.b16 {%0,%1,%2,%3}, [%4];"
                 : "=r"(r0), "=r"(r1), "=r"(r2), "=r"(r3) : "r"(addr));
}

__device__ __forceinline__ void mma16816(float& c0, float& c1, float& c2, float& c3,
                                         uint32_t a0, uint32_t a1, uint32_t a2, uint32_t a3,
                                         uint32_t b0, uint32_t b1) {
    asm volatile("mma.sync.aligned.m16n8k16.row.col.f32.bf16.bf16.f32 "
                 "{%0,%1,%2,%3}, {%4,%5,%6,%7}, {%8,%9}, {%0,%1,%2,%3};"
                 : "+f"(c0), "+f"(c1), "+f"(c2), "+f"(c3)
                 : "r"(a0), "r"(a1), "r"(a2), "r"(a3), "r"(b0), "r"(b1));
}

#define CP_ASYNC16(dst, src) \
    asm volatile("cp.async.cg.shared.global [%0], [%1], 16;" :: "r"(dst), "l"(src))
#define CP_COMMIT() asm volatile("cp.async.commit_group;" ::: "memory")
#define CP_WAIT2()  asm volatile("cp.async.wait_group 2;" ::: "memory")

// ---------------- kernel 1: fused add + RMSNorm -> split bf16 hs' ------------
__global__ void addnorm_kernel(const float* __restrict__ hid,
                               const float* __restrict__ res,
                               const float* __restrict__ w,
                               __nv_bfloat16* __restrict__ hsb,
                               float* __restrict__ resout) {
    int row = blockIdx.x;
    int tid = threadIdx.x;                      // 256 threads, 4 floats each
    const float4* h4 = (const float4*)(hid + (size_t)row * D_MODEL);
    const float4* r4 = (const float4*)(res + (size_t)row * D_MODEL);
    float4 hv = h4[tid];
    float4 rv = r4[tid];
    float4 v;
    v.x = hv.x + rv.x; v.y = hv.y + rv.y; v.z = hv.z + rv.z; v.w = hv.w + rv.w;
    float ss = v.x * v.x + v.y * v.y + v.z * v.z + v.w * v.w;

    __shared__ float red[8];
    #pragma unroll
    for (int o = 16; o > 0; o >>= 1) ss += __shfl_down_sync(0xffffffffu, ss, o);
    int wid = tid >> 5, lane = tid & 31;
    if (lane == 0) red[wid] = ss;
    __syncthreads();
    if (wid == 0) {
        float s = (lane < 8) ? red[lane] : 0.f;
        #pragma unroll
        for (int o = 4; o > 0; o >>= 1) s += __shfl_down_sync(0xffffffffu, s, o);
        if (lane == 0) red[0] = s;
    }
    __syncthreads();
    float scale = rsqrtf(red[0] * (1.f / D_MODEL) + 1e-5f);

    if (resout) ((float4*)(resout + (size_t)row * D_MODEL))[tid] = v;
    float4 wv = ((const float4*)w)[tid];
    float o0 = v.x * scale * wv.x, o1 = v.y * scale * wv.y;
    float o2 = v.z * scale * wv.z, o3 = v.w * scale * wv.w;

    __nv_bfloat16 h0, h1, h2, h3, l0, l1, l2, l3;
    split_bf16(o0, h0, l0); split_bf16(o1, h1, l1);
    split_bf16(o2, h2, l2); split_bf16(o3, h3, l3);
    __nv_bfloat16* base = hsb + (size_t)row * 3 * D_MODEL + tid * 4;
    *(__nv_bfloat162*)(base + 0) = __halves2bfloat162(h0, h1);
    *(__nv_bfloat162*)(base + 2) = __halves2bfloat162(h2, h3);
    *(__nv_bfloat162*)(base + D_MODEL + 0) = __halves2bfloat162(h0, h1);
    *(__nv_bfloat162*)(base + D_MODEL + 2) = __halves2bfloat162(h2, h3);
    *(__nv_bfloat162*)(base + 2 * D_MODEL + 0) = __halves2bfloat162(l0, l1);
    *(__nv_bfloat162*)(base + 2 * D_MODEL + 2) = __halves2bfloat162(l2, l3);
}

// ---------------- weight split+transpose: W[K,N] -> B'[N,3K]=[hi,lo,hi] ------
__global__ void splitB_kernel(const float* __restrict__ W,
                              __nv_bfloat16* __restrict__ out, int K, int N) {
    __shared__ float t[32][33];
    int k0 = blockIdx.y * 32, n0 = blockIdx.x * 32;
    t[threadIdx.y][threadIdx.x] = W[(size_t)(k0 + threadIdx.y) * N + n0 + threadIdx.x];
    __syncthreads();
    float v = t[threadIdx.x][threadIdx.y];      // = W[k0+tx][n0+ty]
    int n = n0 + threadIdx.y, k = k0 + threadIdx.x;
    __nv_bfloat16 hi, lo;
    split_bf16(v, hi, lo);
    size_t o = (size_t)n * 3 * K;
    out[o + k] = hi;
    out[o + K + k] = lo;
    out[o + 2 * K + k] = hi;
}

// ---------------- mma.sync bf16 GEMM, templated N tile -----------------------
// CTA tile 128(M) x BN(N), BK=64 bf16 (128B rows), 3-stage cp.async pipeline.
// 8 warps: warp grid 2(M) x 4(N); warp tile 64 x (BN/4).
// Split-K via blockIdx.z: kStart = z*kLen, output offset z*zStride.
#define STAGES 3

template<int BN>
__global__ __launch_bounds__(256, 1)
void gemm_bf16_kernel(const __nv_bfloat16* __restrict__ A,
                      const __nv_bfloat16* __restrict__ B,
                      float* __restrict__ C,
                      int Kp, int kLen, int ldc, int Nstore,
                      const float* __restrict__ bias, int epilogue,
                      size_t zStride) {
    constexpr int WN = BN / 4;                  // warp N tile (64 or 32)
    constexpr int N8 = WN / 8;                  // n8 groups per warp (8 or 4)
    constexpr int TILE_A = 16384;               // 128 rows x 128B
    constexpr int TILE_B = BN * 128;
    constexpr int STAGE = TILE_A + TILE_B;
    constexpr int AITER = TILE_A / 4096;        // 4
    constexpr int BITER = TILE_B / 4096;        // 8 or 4

    extern __shared__ char smem[];
    uint32_t sb = smem_u32(smem);
    int tid = threadIdx.x;
    int wid = tid >> 5, lane = tid & 31;
    int mBase = blockIdx.y * 128;
    int nBase = blockIdx.x * BN;
    int kStart = blockIdx.z * kLen;
    int m0w = (wid >> 2) * 64;
    int n0w = (wid & 3) * WN;

    const char* Ab = (const char*)A + ((size_t)mBase * Kp + kStart) * 2;
    const char* Bb = (const char*)B + ((size_t)nBase * Kp + kStart) * 2;
    const size_t rowBytes = (size_t)Kp * 2;
    const int nIter = kLen / 64;

    float c[4][N8][4];
    #pragma unroll
    for (int i = 0; i < 4; i++)
        #pragma unroll
        for (int j = 0; j < N8; j++)
            #pragma unroll
            for (int r = 0; r < 4; r++) c[i][j][r] = 0.f;

    // tile loader (lambda-free, macro-ish)
    auto load_tiles = [&](uint32_t st, int kt) {
        const char* As = Ab + (size_t)kt * 128;
        const char* Bs = Bb + (size_t)kt * 128;
        #pragma unroll
        for (int j = 0; j < AITER; j++) {
            int off = (tid + j * 256) * 16;
            int row = off >> 7, bc = off & 127;
            uint32_t sw = (uint32_t)(row * 128 + (bc ^ ((row & 7) << 4)));
            CP_ASYNC16(st + sw, As + (size_t)row * rowBytes + bc);
        }
        #pragma unroll
        for (int j = 0; j < BITER; j++) {
            int off = (tid + j * 256) * 16;
            int row = off >> 7, bc = off & 127;
            uint32_t sw = (uint32_t)(row * 128 + (bc ^ ((row & 7) << 4)));
            CP_ASYNC16(st + TILE_A + sw, Bs + (size_t)row * rowBytes + bc);
        }
        CP_COMMIT();
    };

    int pre = nIter < STAGES ? nIter : STAGES;
    for (int s = 0; s < pre; s++)
        load_tiles(sb + s * STAGE, s);

    int laneM = lane & 15, laneH = lane >> 4;

    for (int i = 0; i < nIter; i++) {
        uint32_t st = sb + (uint32_t)(i % STAGES) * STAGE;
        CP_WAIT2();
        __syncthreads();

        #pragma unroll
        for (int ks = 0; ks < 4; ks++) {
            int bc = ks * 32 + laneH * 16;
            uint32_t a[4][4], b[N8 / 2][4];
            #pragma unroll
            for (int mi = 0; mi < 4; mi++) {
                int row = m0w + mi * 16 + laneM;
                uint32_t ad = st + row * 128 + (bc ^ ((row & 7) << 4));
                ldsm_x4(a[mi][0], a[mi][1], a[mi][2], a[mi][3], ad);
            }
            #pragma unroll
            for (int ng = 0; ng < N8 / 2; ng++) {
                int row = n0w + ng * 16 + laneM;
                uint32_t bd = st + TILE_A + row * 128 + (bc ^ ((row & 7) << 4));
                ldsm_x4(b[ng][0], b[ng][1], b[ng][2], b[ng][3], bd);
            }
            #pragma unroll
            for (int mi = 0; mi < 4; mi++)
                #pragma unroll
                for (int n8 = 0; n8 < N8; n8++) {
                    int ng = n8 >> 1, half = n8 & 1;
                    mma16816(c[mi][n8][0], c[mi][n8][1], c[mi][n8][2], c[mi][n8][3],
                             a[mi][0], a[mi][1], a[mi][2], a[mi][3],
                             b[ng][half], b[ng][half + 2]);
                }
        }
        __syncthreads();
        int nx = i + STAGES;
        if (nx < nIter)
            load_tiles(st, nx);
        else
            CP_COMMIT();                        // empty group keeps wait_group count aligned
    }

    float* Cz = C + zStride * blockIdx.z;
    int rlo = lane >> 2;
    int cc0 = 2 * (lane & 3);
    #pragma unroll
    for (int mi = 0; mi < 4; mi++) {
        int r0 = mBase + m0w + mi * 16 + rlo;
        #pragma unroll
        for (int n8 = 0; n8 < N8; n8++) {
            int col = nBase + n0w + n8 * 8 + cc0;
            if (col < Nstore) {
                float v0 = c[mi][n8][0], v1 = c[mi][n8][1];
                float v2 = c[mi][n8][2], v3 = c[mi][n8][3];
                if (epilogue == 1) {
                    v0 = softplusf(v0 + bias[col]);
                    v1 = softplusf(v1 + bias[col + 1]);
                    v2 = softplusf(v2 + bias[col]);
                    v3 = softplusf(v3 + bias[col + 1]);
                }
                *(float2*)(Cz + (size_t)r0 * ldc + col) = make_float2(v0, v1);
                *(float2*)(Cz + (size_t)(r0 + 8) * ldc + col) = make_float2(v2, v3);
            }
        }
    }
}

// ---------------- xproj split-K reduction (+ fused dtab split) ---------------
__global__ void xreduce_kernel(const float* __restrict__ part,
                               float* __restrict__ xdbl,
                               __nv_bfloat16* __restrict__ dtab) {
    int idx = blockIdx.x * blockDim.x + threadIdx.x;    // < MROWS*96
    if (idx >= MROWS * 96) return;
    int m = idx / 96, j = idx - m * 96;
    float s = 0.f;
    #pragma unroll
    for (int z = 0; z < KSPLIT; z++)
        s += part[(size_t)z * MROWS * 96 + idx];
    xdbl[idx] = s;
    if (j < DT_RANK) {
        __nv_bfloat16 hi, lo;
        split_bf16(s, hi, lo);
        size_t o = (size_t)m * 3 * DT_RANK;
        dtab[o + j] = hi; dtab[o + DT_RANK + j] = hi; dtab[o + 2 * DT_RANK + j] = lo;
    }
}

// ---------------- causal depthwise conv(4) + SiLU -> x fp32 + x' split -------
__global__ void conv_kernel(const float* __restrict__ xz,
                            const float* __restrict__ cw,
                            const float* __restrict__ cb,
                            float* __restrict__ xout,
                            __nv_bfloat16* __restrict__ xb) {
    size_t idx = (size_t)blockIdx.x * blockDim.x + threadIdx.x;
    int d = (int)(idx & (D_INNER - 1));
    int m = (int)(idx >> 11);
    int l = m & (SEQLEN - 1);
    float acc = cb[d];
    #pragma unroll
    for (int k = 0; k < D_CONV; k++) {
        int li = l + k - (D_CONV - 1);
        if (li >= 0)
            acc += xz[(size_t)(m + k - (D_CONV - 1)) * (2 * D_INNER) + d] * cw[d * D_CONV + k];
    }
    acc = acc / (1.f + __expf(-acc));
    xout[idx] = acc;
    __nv_bfloat16 hi, lo;
    split_bf16(acc, hi, lo);
    size_t o = (size_t)m * 3 * D_INNER;
    xb[o + d] = hi; xb[o + D_INNER + d] = hi; xb[o + 2 * D_INNER + d] = lo;
}

// ---------------- scan pass A -------------------------------------------------
__global__ __launch_bounds__(256)
void scanA_kernel(const float* __restrict__ dt, const float* __restrict__ x,
                  const float* __restrict__ xdbl, const float* __restrict__ A_log,
                  float* __restrict__ Pout, float* __restrict__ Sout) {
    int d = blockIdx.x * blockDim.x + threadIdx.x;
    int b = blockIdx.y, c = blockIdx.z;
    float Ae[D_STATE];
    #pragma unroll
    for (int n = 0; n < D_STATE; n++) Ae[n] = -__expf(A_log[d * D_STATE + n]);
    float h[D_STATE] = {};
    float P[D_STATE];
    #pragma unroll
    for (int n = 0; n < D_STATE; n++) P[n] = 1.f;

    int m0 = b * SEQLEN + c * CHUNK;
    for (int t = 0; t < CHUNK; t++) {
        int m = m0 + t;
        float dtv = dt[(size_t)m * D_INNER + d];
        float xv  = x [(size_t)m * D_INNER + d];
        float cb = dtv * xv;
        const float* br = xdbl + (size_t)m * 96 + DT_RANK;
        #pragma unroll
        for (int n = 0; n < D_STATE; n++) {
            float dA = __expf(dtv * Ae[n]);
            P[n] *= dA;
            h[n] = h[n] * dA + cb * br[n];
        }
    }
    size_t o = (((size_t)c * BATCH + b) * D_INNER + d) * D_STATE;
    #pragma unroll
    for (int n = 0; n < D_STATE; n++) { Pout[o + n] = P[n]; Sout[o + n] = h[n]; }
}

// ---------------- chunk combine ----------------------------------------------
__global__ void combine_kernel(const float* __restrict__ P,
                               const float* __restrict__ S,
                               float* __restrict__ H) {
    int idx = blockIdx.x * blockDim.x + threadIdx.x;
    int d = idx & (D_INNER - 1);
    int b = idx >> 11;
    float h[D_STATE] = {};
    for (int c = 0; c < NCHUNK; c++) {
        size_t o = (((size_t)c * BATCH + b) * D_INNER + d) * D_STATE;
        #pragma unroll
        for (int n = 0; n < D_STATE; n++) {
            H[o + n] = h[n];
            h[n] = h[n] * P[o + n] + S[o + n];
        }
    }
}

// ---------------- scan pass C: emit y' split bf16 ----------------------------
__global__ __launch_bounds__(256)
void scanC_kernel(const float* __restrict__ dt, const float* __restrict__ x,
                  const float* __restrict__ xdbl, const float* __restrict__ A_log,
                  const float* __restrict__ H, const float* __restrict__ xz,
                  const float* __restrict__ Dskip, __nv_bfloat16* __restrict__ yb) {
    int d = blockIdx.x * blockDim.x + threadIdx.x;
    int b = blockIdx.y, c = blockIdx.z;
    float Ae[D_STATE];
    #pragma unroll
    for (int n = 0; n < D_STATE; n++) Ae[n] = -__expf(A_log[d * D_STATE + n]);
    float h[D_STATE];
    size_t o = (((size_t)c * BATCH + b) * D_INNER + d) * D_STATE;
    #pragma unroll
    for (int n = 0; n < D_STATE; n++) h[n] = H[o + n];
    float Dv = Dskip[d];

    int m0 = b * SEQLEN + c * CHUNK;
    for (int t = 0; t < CHUNK; t++) {
        int m = m0 + t;
        float dtv = dt[(size_t)m * D_INNER + d];
        float xv  = x [(size_t)m * D_INNER + d];
        float cbv = dtv * xv;
        const float* br = xdbl + (size_t)m * 96 + DT_RANK;
        const float* cr = br + D_STATE;
        float y = 0.f;
        #pragma unroll
        for (int n = 0; n < D_STATE; n++) {
            float dA = __expf(dtv * Ae[n]);
            h[n] = h[n] * dA + cbv * br[n];
            y += h[n] * cr[n];
        }
        float zv = xz[(size_t)m * (2 * D_INNER) + D_INNER + d];
        float sz = zv / (1.f + __expf(-zv));
        float yv = (y + xv * Dv) * sz;
        __nv_bfloat16 hi, lo;
        split_bf16(yv, hi, lo);
        size_t oy = (size_t)m * 3 * D_INNER;
        yb[oy + d] = hi; yb[oy + D_INNER + d] = hi; yb[oy + 2 * D_INNER + d] = lo;
    }
}

// ---------------- launch ------------------------------------------------------
extern "C" void kernel_launch(void* const* d_in, const int* in_sizes, int n_in,
                              void* d_out, int out_size) {
    const float* hidden   = (const float*)d_in[0];
    const float* residual = (const float*)d_in[1];
    const float* norm_w   = (const float*)d_in[2];
    const float* in_proj  = (const float*)d_in[3];
    const float* conv_w   = (const float*)d_in[4];
    const float* conv_b   = (const float*)d_in[5];
    const float* x_proj   = (const float*)d_in[6];
    const float* dt_proj  = (const float*)d_in[7];
    const float* dt_b     = (const float*)d_in[8];
    const float* A_log    = (const float*)d_in[9];
    const float* D_skip   = (const float*)d_in[10];
    const float* out_proj = (const float*)d_in[11];
    float* out = (float*)d_out;

    float *xz, *x, *xdbl, *xpart, *dt, *P, *S, *H;
    __nv_bfloat16 *hsb, *xb, *yb, *dtab, *wib, *wxb, *wdb, *wob;
    cudaGetSymbolAddress((void**)&xz,    g_xz);
    cudaGetSymbolAddress((void**)&x,     g_x);
    cudaGetSymbolAddress((void**)&xdbl,  g_xdbl);
    cudaGetSymbolAddress((void**)&xpart, g_xpart);
    cudaGetSymbolAddress((void**)&dt,    g_dt);
    cudaGetSymbolAddress((void**)&P,     g_P);
    cudaGetSymbolAddress((void**)&S,     g_S);
    cudaGetSymbolAddress((void**)&H,     g_H);
    cudaGetSymbolAddress((void**)&hsb,   g_hsb);
    cudaGetSymbolAddress((void**)&xb,    g_xb);
    cudaGetSymbolAddress((void**)&yb,    g_yb);
    cudaGetSymbolAddress((void**)&dtab,  g_dtab);
    cudaGetSymbolAddress((void**)&wib,   g_wib);
    cudaGetSymbolAddress((void**)&wxb,   g_wxb);
    cudaGetSymbolAddress((void**)&wdb,   g_wdb);
    cudaGetSymbolAddress((void**)&wob,   g_wob);

    const int SMEM256 = STAGES * (16384 + 256 * 128);   // 144 KB
    const int SMEM128 = STAGES * (16384 + 128 * 128);   // 96 KB
    cudaFuncSetAttribute(gemm_bf16_kernel<256>, cudaFuncAttributeMaxDynamicSharedMemorySize, SMEM256);
    cudaFuncSetAttribute(gemm_bf16_kernel<128>, cudaFuncAttributeMaxDynamicSharedMemorySize, SMEM128);

    const int OUT1 = MROWS * D_MODEL;
    float* resout = (out_size >= 2 * OUT1) ? out + OUT1 : nullptr;

    dim3 b32(32, 32);

    // weight splits (independent of activations; issue first)
    splitB_kernel<<<dim3(2 * D_INNER / 32, D_MODEL / 32), b32>>>(in_proj, wib, D_MODEL, 2 * D_INNER);
    splitB_kernel<<<dim3(96 / 32, D_INNER / 32), b32>>>(x_proj, wxb, D_INNER, 96);
    splitB_kernel<<<dim3(D_INNER / 32, DT_RANK / 32), b32>>>(dt_proj, wdb, DT_RANK, D_INNER);
    splitB_kernel<<<dim3(D_MODEL / 32, D_INNER / 32), b32>>>(out_proj, wob, D_INNER, D_MODEL);

    // 1. add + RMSNorm -> hs' (and residual output)
    addnorm_kernel<<<MROWS, 256>>>(hidden, residual, norm_w, hsb, resout);

    // 2. xz = hs @ in_proj_w   (M=4096, N=4096, Kp=3072) — 128x256 tiles
    gemm_bf16_kernel<256><<<dim3(2 * D_INNER / 256, MROWS / 128), 256, SMEM256>>>(
        hsb, wib, xz, 3 * D_MODEL, 3 * D_MODEL, 2 * D_INNER, 2 * D_INNER, nullptr, 0, 0);

    // 3. conv + SiLU -> x fp32 + x' split
    conv_kernel<<<(MROWS * D_INNER) / 256, 256>>>(xz, conv_w, conv_b, x, xb);

    // 4. x_dbl = x @ x_proj_w (N padded 128, split-K x8: Kp=6144, kLen=768)
    gemm_bf16_kernel<128><<<dim3(1, MROWS / 128, KSPLIT), 256, SMEM128>>>(
        xb, wxb, xpart, 3 * D_INNER, 3 * D_INNER / KSPLIT, 96, 96, nullptr, 0,
        (size_t)MROWS * 96);
    xreduce_kernel<<<(MROWS * 96 + 255) / 256, 256>>>(xpart, xdbl, dtab);

    // 5. dt = softplus(x_dbl[:, :64] @ dt_proj_w + dt_b)  (Kp=192) — 128x256
    gemm_bf16_kernel<256><<<dim3(D_INNER / 256, MROWS / 128), 256, SMEM256>>>(
        dtab, wdb, dt, 3 * DT_RANK, 3 * DT_RANK, D_INNER, D_INNER, dt_b, 1, 0);

    // 6. selective scan: chunked 3-pass (scanC emits y' split)
    scanA_kernel<<<dim3(D_INNER / 256, BATCH, NCHUNK), 256>>>(dt, x, xdbl, A_log, P, S);
    combine_kernel<<<(BATCH * D_INNER) / 256, 256>>>(P, S, H);
    scanC_kernel<<<dim3(D_INNER / 256, BATCH, NCHUNK), 256>>>(dt, x, xdbl, A_log, H, xz, D_skip, yb);

    // 7. out = y @ out_proj_w  (Kp=6144) — 128x256 tiles
    gemm_bf16_kernel<256><<<dim3(D_MODEL / 256, MROWS / 128), 256, SMEM256>>>(
        yb, wob, out, 3 * D_INNER, 3 * D_INNER, D_MODEL, D_MODEL, nullptr, 0, 0);
}